// round 6
// baseline (speedup 1.0000x reference)
#include <cuda_runtime.h>
#include <math.h>

#define NGRAPHS 2048
#define NPG     32
#define EPG     256
#define INDIM   128
#define HOUT    256     // 4 heads * 64
#define HSR     260     // hs/hd row stride: mult of 4 (float4), 260/4=65 odd -> rows spread banks
#define XSR     36      // k-major input stride (mult of 4)
#define ELS     5       // elog stride (scalar, conflict-free)
#define NTHREADS 1024

__device__ __forceinline__ float2 ffma2(float2 a, float2 b, float2 c) {
    float2 d;
    asm("fma.rn.f32x2 %0, %1, %2, %3;"
        : "=l"(*(unsigned long long*)&d)
        : "l"(*(unsigned long long*)&a),
          "l"(*(unsigned long long*)&b),
          "l"(*(unsigned long long*)&c));
    return d;
}
// acc += s * v (float4 via 2x ffma2)
__device__ __forceinline__ void fma4(float4& acc, float s, float4 v) {
    float2 s2 = make_float2(s, s);
    float2 lo = ffma2(make_float2(v.x, v.y), s2, make_float2(acc.x, acc.y));
    float2 hi = ffma2(make_float2(v.z, v.w), s2, make_float2(acc.z, acc.w));
    acc.x = lo.x; acc.y = lo.y; acc.z = hi.x; acc.w = hi.y;
}

#define SMEM_FLOATS (32*HSR*2 + 8192 + 64*XSR + 256 + 128 + 32)
#define SMEM_INTS   (256 + 256 + 32 + 33 + 32 + 256)
#define SMEM_BYTES  ((SMEM_FLOATS + SMEM_INTS) * 4)

// Dual GEMM, 1024 threads. m=tid>>9; within 512: cg=r>>3 (4 cols), ng=r&7 (4 nodes).
// Per k: 1 LDS.128 (x, 4 nodes) + 1 LDG.128 (W, 4 cols) + 8 FFMA2.
template<int K>
__device__ __forceinline__ void gemm_dual(
    const float* __restrict__ Ws, const float* __restrict__ bsv,
    const float* __restrict__ Wd, const float* __restrict__ bdv,
    const float* xT, float* hs, float* hd, int tid)
{
    const int m  = tid >> 9;
    const int r  = tid & 511;
    const int cg = r >> 3;    // 0..63 -> j0 = cg*4
    const int ng = r & 7;     // 0..7  -> nodes ng*4..ng*4+3
    const float* W  = m ? Wd  : Ws;
    const float* bv = m ? bdv : bsv;
    float* out      = m ? hd  : hs;
    const int j0 = cg * 4;

    float2 acc[4][2];
#pragma unroll
    for (int c = 0; c < 4; c++) {
        float b = __ldg(bv + j0 + c);
        acc[c][0] = make_float2(b, b);
        acc[c][1] = make_float2(b, b);
    }
    const float4* xb = (const float4*)xT + ng;   // + k*(XSR/4)
    const float4* Wb = (const float4*)W + cg;    // + k*(HOUT/4)
#pragma unroll 4
    for (int k = 0; k < K; k++) {
        float4 w  = __ldg(Wb + k * (HOUT/4));
        float4 xv = xb[k * (XSR/4)];
        float2 xlo = make_float2(xv.x, xv.y);
        float2 xhi = make_float2(xv.z, xv.w);
        acc[0][0] = ffma2(xlo, make_float2(w.x, w.x), acc[0][0]);
        acc[0][1] = ffma2(xhi, make_float2(w.x, w.x), acc[0][1]);
        acc[1][0] = ffma2(xlo, make_float2(w.y, w.y), acc[1][0]);
        acc[1][1] = ffma2(xhi, make_float2(w.y, w.y), acc[1][1]);
        acc[2][0] = ffma2(xlo, make_float2(w.z, w.z), acc[2][0]);
        acc[2][1] = ffma2(xhi, make_float2(w.z, w.z), acc[2][1]);
        acc[3][0] = ffma2(xlo, make_float2(w.w, w.w), acc[3][0]);
        acc[3][1] = ffma2(xhi, make_float2(w.w, w.w), acc[3][1]);
    }
    // bank-bijective store: cc = (c + (ng>>1)) & 3
#pragma unroll
    for (int c = 0; c < 4; c++) {
        int cc = (c + (ng >> 1)) & 3;
#pragma unroll
        for (int ii = 0; ii < 2; ii++) {
            out[(ng*4 + 2*ii)  * HSR + j0 + cc] = acc[cc][ii].x;
            out[(ng*4 + 2*ii+1)* HSR + j0 + cc] = acc[cc][ii].y;
        }
    }
}

// logits -> per-(dst,head) softmax (CSR) -> aggregation
__device__ __forceinline__ void attention_block(
    const float* hs, const float* hd, const float* avec,
    float* elog, float* invd, float* agg,
    const int* esrc, const int* edst, const int* cnt, const int* coff,
    const int* elist, int tid)
{
    // ---- edge logits: 1024 threads = 256 edges x 4 heads ----
    {
        int e = tid & 255;
        int h = tid >> 8;
        int s = esrc[e], t = edst[e];
        const float4* ps = (const float4*)(hs + s * HSR) + h * 16;
        const float4* pd = (const float4*)(hd + t * HSR) + h * 16;
        const float4* pa = (const float4*)avec + h * 16;
        float f1a = 0.f, f1b = 0.f, f2a = 0.f, f2b = 0.f;
#pragma unroll 4
        for (int i = 0; i < 16; i++) {
            float4 vs = ps[i], vd = pd[i], av = pa[i];
            float vx = vs.x + vd.x, vy = vs.y + vd.y;
            float vz = vs.z + vd.z, vw = vs.w + vd.w;
            f1a = fmaf(av.x, vx, f1a); f1b = fmaf(av.y, vy, f1b);
            f1a = fmaf(av.z, vz, f1a); f1b = fmaf(av.w, vw, f1b);
            f2a = fmaf(av.x, fabsf(vx), f2a); f2b = fmaf(av.y, fabsf(vy), f2b);
            f2a = fmaf(av.z, fabsf(vz), f2a); f2b = fmaf(av.w, fabsf(vw), f2b);
        }
        // leaky_relu slope 0.2: a.lrelu(v) = 0.6*(a.v) + 0.4*(a.|v|)
        elog[e*ELS + h] = 0.6f*(f1a + f1b) + 0.4f*(f2a + f2b);
    }
    __syncthreads();

    // ---- softmax per (dst node, head): 128 workers ----
    if (tid < 128) {
        int n = tid >> 2, h = tid & 3;
        int b = coff[n], c = cnt[n];
        float m = -1e30f;
        for (int i = 0; i < c; i++) m = fmaxf(m, elog[elist[b+i]*ELS + h]);
        float den = 0.f;
        for (int i = 0; i < c; i++) {
            int e = elist[b+i];
            float ex = __expf(elog[e*ELS + h] - m);
            elog[e*ELS + h] = ex;
            den += ex;
        }
        invd[tid] = c ? (1.f / den) : 0.f;
    }
    __syncthreads();

    // ---- aggregation: warp per node; lane owns 8 dims (2 float4, parity-rotated) ----
    {
        int n = tid >> 5, lane = tid & 31;
        int h = lane >> 3, dsub = lane & 7;
        int b = coff[n], c = cnt[n];
        float iv = invd[n*4 + h];
        const int i0 = (dsub + h) & 1, i1 = i0 ^ 1;
        float4 accA = make_float4(0.f,0.f,0.f,0.f);
        float4 accB = make_float4(0.f,0.f,0.f,0.f);
        for (int i = 0; i < c; i++) {
            int e  = elist[b+i];
            int s2 = esrc[e];
            float al = elog[e*ELS + h] * iv;
            const float4* pr = (const float4*)(hs + s2*HSR) + h*16 + dsub*2;
            float4 v0 = pr[i0];
            float4 v1 = pr[i1];
            fma4(accA, al, v0);
            fma4(accB, al, v1);
        }
        float4* po = (float4*)(agg + n*HOUT) + h*16 + dsub*2;
        po[i0] = accA;
        po[i1] = accB;
    }
    __syncthreads();
}

__global__ void __launch_bounds__(NTHREADS, 1)
gat_fused_kernel(const float* __restrict__ x,
                 const int* __restrict__ src, const int* __restrict__ dst,
                 const float* __restrict__ W1s, const float* __restrict__ b1s,
                 const float* __restrict__ W1d, const float* __restrict__ b1d,
                 const float* __restrict__ a1,
                 const float* __restrict__ W2s, const float* __restrict__ b2s,
                 const float* __restrict__ W2d, const float* __restrict__ b2d,
                 const float* __restrict__ a2,
                 const float* __restrict__ Wg, const float* __restrict__ bg,
                 float* __restrict__ out)
{
    extern __shared__ float smem[];
    float* hs     = smem;
    float* hd     = hs + 32*HSR;
    float* agg    = hd + 32*HSR;     // 8192 (xT stride 36 for layer-1 GEMM; agg [32][256])
    float* hbuf   = agg + 8192;      // 64*36 = 2304; elog aliases first 1280
    float* elog   = hbuf;
    float* avec   = hbuf + 64*XSR;   // 256
    float* invd   = avec + 256;      // 128
    float* alphaS = invd + 128;      // 32
    int* esrc  = (int*)(alphaS + 32);
    int* edst  = esrc + EPG;
    int* cnt   = edst + EPG;
    int* coff  = cnt + 32;
    int* fill  = coff + 33;
    int* elist = fill + 32;

    const int g = blockIdx.x;
    const int tid = threadIdx.x;

    if (tid < 32) { cnt[tid] = 0; fill[tid] = 0; }
    __syncthreads();

    int myT = -1;
    if (tid < 256) {
        int s = src[g*EPG + tid] - g*NPG;
        int t = dst[g*EPG + tid] - g*NPG;
        esrc[tid] = s;
        edst[tid] = t;
        myT = t;
        atomicAdd(&cnt[t], 1);
    }
    // x -> xT[k*36 + n]: coalesced float4 LDG, then 4 scalar STS (2-way max)
    {
        int n  = tid >> 5;          // 0..31
        int kq = tid & 31;          // float4 group 0..31
        float4 v = __ldg((const float4*)x + (g*NPG + n)*(INDIM/4) + kq);
        int k0 = kq * 4;
        agg[(k0+0)*XSR + n] = v.x;
        agg[(k0+1)*XSR + n] = v.y;
        agg[(k0+2)*XSR + n] = v.z;
        agg[(k0+3)*XSR + n] = v.w;
    }
    if (tid < 256) avec[tid] = a1[tid];
    __syncthreads();

    if (tid == 0) {
        int s = 0;
        for (int i = 0; i < 32; i++) { coff[i] = s; s += cnt[i]; }
        coff[32] = s;
    }
    __syncthreads();
    if (tid < 256) {
        int pos = coff[myT] + atomicAdd(&fill[myT], 1);
        elist[pos] = tid;
    }

    // ---- layer 1 ----
    gemm_dual<INDIM>(W1s, b1s, W1d, b1d, agg, hs, hd, tid);
    __syncthreads();
    attention_block(hs, hd, avec, elog, invd, agg, esrc, edst, cnt, coff, elist, tid);

    // head maxpool -> hbuf[d*36 + n] (k-major for layer-2 GEMM); d-fast reads
    for (int i = tid; i < NPG*64; i += NTHREADS) {
        int n = i >> 6, d = i & 63;
        const float* ar = agg + n*HOUT + d;
        float m = fmaxf(fmaxf(ar[0], ar[64]), fmaxf(ar[128], ar[192]));
        hbuf[d*XSR + n] = m;
    }
    if (tid < 256) avec[tid] = a2[tid];
    __syncthreads();

    // ---- layer 2 ----
    gemm_dual<64>(W2s, b2s, W2d, b2d, hbuf, hs, hd, tid);
    __syncthreads();
    attention_block(hs, hd, avec, elog, invd, agg, esrc, edst, cnt, coff, elist, tid);

    // head maxpool -> hbuf[n*64 + d] row-major
    for (int i = tid; i < NPG*64; i += NTHREADS) {
        int n = i >> 6, d = i & 63;
        const float* ar = agg + n*HOUT + d;
        float m = fmaxf(fmaxf(ar[0], ar[64]), fmaxf(ar[128], ar[192]));
        hbuf[n*64 + d] = m;
    }
    __syncthreads();

    // ---- global attention pooling ----
    if (tid < 32) {
        int n = tid;
        float acc = __ldg(bg);
        const float* hr = hbuf + n*64;
#pragma unroll 8
        for (int d = 0; d < 64; d++) acc = fmaf(hr[d], __ldg(Wg + d), acc);
        float m = acc;
#pragma unroll
        for (int off = 16; off > 0; off >>= 1)
            m = fmaxf(m, __shfl_xor_sync(0xffffffffu, m, off));
        float ex = __expf(acc - m);
        float den = ex;
#pragma unroll
        for (int off = 16; off > 0; off >>= 1)
            den += __shfl_xor_sync(0xffffffffu, den, off);
        alphaS[n] = ex / den;
    }
    __syncthreads();
    if (tid < 64) {
        int d = tid;
        float o = 0.f;
#pragma unroll 8
        for (int n = 0; n < 32; n++) o = fmaf(alphaS[n], hbuf[n*64 + d], o);
        out[g*64 + d] = o;
    }
}

extern "C" void kernel_launch(void* const* d_in, const int* in_sizes, int n_in,
                              void* d_out, int out_size) {
    const float* x   = (const float*)d_in[0];
    const int*   src = (const int*)d_in[1];
    const int*   dst = (const int*)d_in[2];
    const float* W1s = (const float*)d_in[4];
    const float* b1s = (const float*)d_in[5];
    const float* W1d = (const float*)d_in[6];
    const float* b1d = (const float*)d_in[7];
    const float* a1  = (const float*)d_in[8];
    const float* W2s = (const float*)d_in[9];
    const float* b2s = (const float*)d_in[10];
    const float* W2d = (const float*)d_in[11];
    const float* b2d = (const float*)d_in[12];
    const float* a2  = (const float*)d_in[13];
    const float* Wg  = (const float*)d_in[14];
    const float* bg  = (const float*)d_in[15];
    float* out = (float*)d_out;

    cudaFuncSetAttribute(gat_fused_kernel,
                         cudaFuncAttributeMaxDynamicSharedMemorySize, SMEM_BYTES);
    gat_fused_kernel<<<NGRAPHS, NTHREADS, SMEM_BYTES>>>(
        x, src, dst, W1s, b1s, W1d, b1d, a1,
        W2s, b2s, W2d, b2d, a2, Wg, bg, out);
}

// round 7
// speedup vs baseline: 1.0003x; 1.0003x over previous
#include <cuda_runtime.h>
#include <math.h>

#define NGRAPHS 2048
#define NPG     32
#define EPG     256
#define INDIM   128
#define HOUT    256     // 4 heads * 64
#define HSR     260     // hs/hd row stride: mult of 4 (float4), 260/4=65 odd -> rows spread banks
#define XSR     36      // k-major input stride (mult of 4)
#define ELS     5       // elog stride (scalar, conflict-free)
#define NTHREADS 1024

__device__ __forceinline__ float2 ffma2(float2 a, float2 b, float2 c) {
    float2 d;
    asm("fma.rn.f32x2 %0, %1, %2, %3;"
        : "=l"(*(unsigned long long*)&d)
        : "l"(*(unsigned long long*)&a),
          "l"(*(unsigned long long*)&b),
          "l"(*(unsigned long long*)&c));
    return d;
}
// acc += s * v (float4 via 2x ffma2)
__device__ __forceinline__ void fma4(float4& acc, float s, float4 v) {
    float2 s2 = make_float2(s, s);
    float2 lo = ffma2(make_float2(v.x, v.y), s2, make_float2(acc.x, acc.y));
    float2 hi = ffma2(make_float2(v.z, v.w), s2, make_float2(acc.z, acc.w));
    acc.x = lo.x; acc.y = lo.y; acc.z = hi.x; acc.w = hi.y;
}

#define SMEM_FLOATS (32*HSR*2 + 8192 + 64*XSR + 256 + 128 + 32)
#define SMEM_INTS   (256 + 256 + 32 + 33 + 32 + 256)
#define SMEM_BYTES  ((SMEM_FLOATS + SMEM_INTS) * 4)

// Dual GEMM, 1024 threads. m=tid>>9; within 512: cg=r>>3 (4 cols), ng=r&7 (4 nodes).
// Per k: 1 LDS.128 (x, 4 nodes) + 1 LDG.128 (W, 4 cols) + 8 FFMA2.
template<int K>
__device__ __forceinline__ void gemm_dual(
    const float* __restrict__ Ws, const float* __restrict__ bsv,
    const float* __restrict__ Wd, const float* __restrict__ bdv,
    const float* xT, float* hs, float* hd, int tid)
{
    const int m  = tid >> 9;
    const int r  = tid & 511;
    const int cg = r >> 3;    // 0..63 -> j0 = cg*4
    const int ng = r & 7;     // 0..7  -> nodes ng*4..ng*4+3
    const float* W  = m ? Wd  : Ws;
    const float* bv = m ? bdv : bsv;
    float* out      = m ? hd  : hs;
    const int j0 = cg * 4;

    float2 acc[4][2];
#pragma unroll
    for (int c = 0; c < 4; c++) {
        float b = __ldg(bv + j0 + c);
        acc[c][0] = make_float2(b, b);
        acc[c][1] = make_float2(b, b);
    }
    const float4* xb = (const float4*)xT + ng;   // + k*(XSR/4)
    const float4* Wb = (const float4*)W + cg;    // + k*(HOUT/4)
#pragma unroll 4
    for (int k = 0; k < K; k++) {
        float4 w  = __ldg(Wb + k * (HOUT/4));
        float4 xv = xb[k * (XSR/4)];
        float2 xlo = make_float2(xv.x, xv.y);
        float2 xhi = make_float2(xv.z, xv.w);
        acc[0][0] = ffma2(xlo, make_float2(w.x, w.x), acc[0][0]);
        acc[0][1] = ffma2(xhi, make_float2(w.x, w.x), acc[0][1]);
        acc[1][0] = ffma2(xlo, make_float2(w.y, w.y), acc[1][0]);
        acc[1][1] = ffma2(xhi, make_float2(w.y, w.y), acc[1][1]);
        acc[2][0] = ffma2(xlo, make_float2(w.z, w.z), acc[2][0]);
        acc[2][1] = ffma2(xhi, make_float2(w.z, w.z), acc[2][1]);
        acc[3][0] = ffma2(xlo, make_float2(w.w, w.w), acc[3][0]);
        acc[3][1] = ffma2(xhi, make_float2(w.w, w.w), acc[3][1]);
    }
    // bank-bijective store: cc = (c + (ng>>1)) & 3
#pragma unroll
    for (int c = 0; c < 4; c++) {
        int cc = (c + (ng >> 1)) & 3;
#pragma unroll
        for (int ii = 0; ii < 2; ii++) {
            out[(ng*4 + 2*ii)  * HSR + j0 + cc] = acc[cc][ii].x;
            out[(ng*4 + 2*ii+1)* HSR + j0 + cc] = acc[cc][ii].y;
        }
    }
}

// logits -> per-(dst,head) softmax (CSR) -> aggregation
__device__ __forceinline__ void attention_block(
    const float* hs, const float* hd, const float* avec,
    float* elog, float* invd, float* agg,
    const int* esrc, const int* edst, const int* cnt, const int* coff,
    const int* elist, int tid)
{
    // ---- edge logits: 1024 threads = 256 edges x 4 heads ----
    {
        int e = tid & 255;
        int h = tid >> 8;
        int s = esrc[e], t = edst[e];
        const float4* ps = (const float4*)(hs + s * HSR) + h * 16;
        const float4* pd = (const float4*)(hd + t * HSR) + h * 16;
        const float4* pa = (const float4*)avec + h * 16;
        float f1a = 0.f, f1b = 0.f, f2a = 0.f, f2b = 0.f;
#pragma unroll 4
        for (int i = 0; i < 16; i++) {
            float4 vs = ps[i], vd = pd[i], av = pa[i];
            float vx = vs.x + vd.x, vy = vs.y + vd.y;
            float vz = vs.z + vd.z, vw = vs.w + vd.w;
            f1a = fmaf(av.x, vx, f1a); f1b = fmaf(av.y, vy, f1b);
            f1a = fmaf(av.z, vz, f1a); f1b = fmaf(av.w, vw, f1b);
            f2a = fmaf(av.x, fabsf(vx), f2a); f2b = fmaf(av.y, fabsf(vy), f2b);
            f2a = fmaf(av.z, fabsf(vz), f2a); f2b = fmaf(av.w, fabsf(vw), f2b);
        }
        // leaky_relu slope 0.2: a.lrelu(v) = 0.6*(a.v) + 0.4*(a.|v|)
        elog[e*ELS + h] = 0.6f*(f1a + f1b) + 0.4f*(f2a + f2b);
    }
    __syncthreads();

    // ---- softmax per (dst node, head): 128 workers ----
    if (tid < 128) {
        int n = tid >> 2, h = tid & 3;
        int b = coff[n], c = cnt[n];
        float m = -1e30f;
        for (int i = 0; i < c; i++) m = fmaxf(m, elog[elist[b+i]*ELS + h]);
        float den = 0.f;
        for (int i = 0; i < c; i++) {
            int e = elist[b+i];
            float ex = __expf(elog[e*ELS + h] - m);
            elog[e*ELS + h] = ex;
            den += ex;
        }
        invd[tid] = c ? (1.f / den) : 0.f;
    }
    __syncthreads();

    // ---- aggregation: warp per node; lane owns 8 dims (2 float4, parity-rotated) ----
    {
        int n = tid >> 5, lane = tid & 31;
        int h = lane >> 3, dsub = lane & 7;
        int b = coff[n], c = cnt[n];
        float iv = invd[n*4 + h];
        const int i0 = (dsub + h) & 1, i1 = i0 ^ 1;
        float4 accA = make_float4(0.f,0.f,0.f,0.f);
        float4 accB = make_float4(0.f,0.f,0.f,0.f);
        for (int i = 0; i < c; i++) {
            int e  = elist[b+i];
            int s2 = esrc[e];
            float al = elog[e*ELS + h] * iv;
            const float4* pr = (const float4*)(hs + s2*HSR) + h*16 + dsub*2;
            float4 v0 = pr[i0];
            float4 v1 = pr[i1];
            fma4(accA, al, v0);
            fma4(accB, al, v1);
        }
        float4* po = (float4*)(agg + n*HOUT) + h*16 + dsub*2;
        po[i0] = accA;
        po[i1] = accB;
    }
    __syncthreads();
}

__global__ void __launch_bounds__(NTHREADS, 1)
gat_fused_kernel(const float* __restrict__ x,
                 const int* __restrict__ src, const int* __restrict__ dst,
                 const float* __restrict__ W1s, const float* __restrict__ b1s,
                 const float* __restrict__ W1d, const float* __restrict__ b1d,
                 const float* __restrict__ a1,
                 const float* __restrict__ W2s, const float* __restrict__ b2s,
                 const float* __restrict__ W2d, const float* __restrict__ b2d,
                 const float* __restrict__ a2,
                 const float* __restrict__ Wg, const float* __restrict__ bg,
                 float* __restrict__ out)
{
    extern __shared__ float smem[];
    float* hs     = smem;
    float* hd     = hs + 32*HSR;
    float* agg    = hd + 32*HSR;     // 8192 (xT stride 36 for layer-1 GEMM; agg [32][256])
    float* hbuf   = agg + 8192;      // 64*36 = 2304; elog aliases first 1280
    float* elog   = hbuf;
    float* avec   = hbuf + 64*XSR;   // 256
    float* invd   = avec + 256;      // 128
    float* alphaS = invd + 128;      // 32
    int* esrc  = (int*)(alphaS + 32);
    int* edst  = esrc + EPG;
    int* cnt   = edst + EPG;
    int* coff  = cnt + 32;
    int* fill  = coff + 33;
    int* elist = fill + 32;

    const int g = blockIdx.x;
    const int tid = threadIdx.x;

    if (tid < 32) { cnt[tid] = 0; fill[tid] = 0; }
    __syncthreads();

    int myT = -1;
    if (tid < 256) {
        int s = src[g*EPG + tid] - g*NPG;
        int t = dst[g*EPG + tid] - g*NPG;
        esrc[tid] = s;
        edst[tid] = t;
        myT = t;
        atomicAdd(&cnt[t], 1);
    }
    // x -> xT[k*36 + n]: coalesced float4 LDG, then 4 scalar STS (2-way max)
    {
        int n  = tid >> 5;          // 0..31
        int kq = tid & 31;          // float4 group 0..31
        float4 v = __ldg((const float4*)x + (g*NPG + n)*(INDIM/4) + kq);
        int k0 = kq * 4;
        agg[(k0+0)*XSR + n] = v.x;
        agg[(k0+1)*XSR + n] = v.y;
        agg[(k0+2)*XSR + n] = v.z;
        agg[(k0+3)*XSR + n] = v.w;
    }
    if (tid < 256) avec[tid] = a1[tid];
    __syncthreads();

    if (tid == 0) {
        int s = 0;
        for (int i = 0; i < 32; i++) { coff[i] = s; s += cnt[i]; }
        coff[32] = s;
    }
    __syncthreads();
    if (tid < 256) {
        int pos = coff[myT] + atomicAdd(&fill[myT], 1);
        elist[pos] = tid;
    }

    // ---- layer 1 ----
    gemm_dual<INDIM>(W1s, b1s, W1d, b1d, agg, hs, hd, tid);
    __syncthreads();
    attention_block(hs, hd, avec, elog, invd, agg, esrc, edst, cnt, coff, elist, tid);

    // head maxpool -> hbuf[d*36 + n] (k-major for layer-2 GEMM); d-fast reads
    for (int i = tid; i < NPG*64; i += NTHREADS) {
        int n = i >> 6, d = i & 63;
        const float* ar = agg + n*HOUT + d;
        float m = fmaxf(fmaxf(ar[0], ar[64]), fmaxf(ar[128], ar[192]));
        hbuf[d*XSR + n] = m;
    }
    if (tid < 256) avec[tid] = a2[tid];
    __syncthreads();

    // ---- layer 2 ----
    gemm_dual<64>(W2s, b2s, W2d, b2d, hbuf, hs, hd, tid);
    __syncthreads();
    attention_block(hs, hd, avec, elog, invd, agg, esrc, edst, cnt, coff, elist, tid);

    // head maxpool -> hbuf[n*64 + d] row-major
    for (int i = tid; i < NPG*64; i += NTHREADS) {
        int n = i >> 6, d = i & 63;
        const float* ar = agg + n*HOUT + d;
        float m = fmaxf(fmaxf(ar[0], ar[64]), fmaxf(ar[128], ar[192]));
        hbuf[n*64 + d] = m;
    }
    __syncthreads();

    // ---- global attention pooling ----
    if (tid < 32) {
        int n = tid;
        float acc = __ldg(bg);
        const float* hr = hbuf + n*64;
#pragma unroll 8
        for (int d = 0; d < 64; d++) acc = fmaf(hr[d], __ldg(Wg + d), acc);
        float m = acc;
#pragma unroll
        for (int off = 16; off > 0; off >>= 1)
            m = fmaxf(m, __shfl_xor_sync(0xffffffffu, m, off));
        float ex = __expf(acc - m);
        float den = ex;
#pragma unroll
        for (int off = 16; off > 0; off >>= 1)
            den += __shfl_xor_sync(0xffffffffu, den, off);
        alphaS[n] = ex / den;
    }
    __syncthreads();
    if (tid < 64) {
        int d = tid;
        float o = 0.f;
#pragma unroll 8
        for (int n = 0; n < 32; n++) o = fmaf(alphaS[n], hbuf[n*64 + d], o);
        out[g*64 + d] = o;
    }
}

extern "C" void kernel_launch(void* const* d_in, const int* in_sizes, int n_in,
                              void* d_out, int out_size) {
    const float* x   = (const float*)d_in[0];
    const int*   src = (const int*)d_in[1];
    const int*   dst = (const int*)d_in[2];
    const float* W1s = (const float*)d_in[4];
    const float* b1s = (const float*)d_in[5];
    const float* W1d = (const float*)d_in[6];
    const float* b1d = (const float*)d_in[7];
    const float* a1  = (const float*)d_in[8];
    const float* W2s = (const float*)d_in[9];
    const float* b2s = (const float*)d_in[10];
    const float* W2d = (const float*)d_in[11];
    const float* b2d = (const float*)d_in[12];
    const float* a2  = (const float*)d_in[13];
    const float* Wg  = (const float*)d_in[14];
    const float* bg  = (const float*)d_in[15];
    float* out = (float*)d_out;

    cudaFuncSetAttribute(gat_fused_kernel,
                         cudaFuncAttributeMaxDynamicSharedMemorySize, SMEM_BYTES);
    gat_fused_kernel<<<NGRAPHS, NTHREADS, SMEM_BYTES>>>(
        x, src, dst, W1s, b1s, W1d, b1d, a1,
        W2s, b2s, W2d, b2d, a2, Wg, bg, out);
}